// round 2
// baseline (speedup 1.0000x reference)
#include <cuda_runtime.h>
#include <cstdint>

// Problem constants
#define BB    16
#define PP    512
#define LLAY  12
#define HHEAD 12
#define DHH   64
#define MS    13          // mlp streams
#define DD    768
#define KTOT  9216        // L*H*DH
#define LH    144         // L*H

// GEMM tiling
#define BM 128
#define BN 64
#define BK 32
#define NTHREADS 256

// Per-batch constant vector scratch (no allocation allowed -> __device__ global)
__device__ float g_cvec[BB * DD];

// cvec[b,d] = post_bias[d] + sum_m (1-mlp_mask[b,m])*mlp_constants[m,d]
//           + sum_lh (1-attn_mask[b,lh])*attn_constants[lh,d]
__global__ void prep_kernel(const float* __restrict__ mlp_mask,
                            const float* __restrict__ attn_mask,
                            const float* __restrict__ mlp_constants,
                            const float* __restrict__ attn_constants,
                            const float* __restrict__ post_bias) {
    int b = blockIdx.x;
    int d = threadIdx.x;  // 768 threads
    float acc = post_bias[d];
#pragma unroll
    for (int m = 0; m < MS; m++)
        acc += (1.0f - mlp_mask[b * MS + m]) * mlp_constants[m * DD + d];
    for (int lh = 0; lh < LH; lh++)
        acc += (1.0f - attn_mask[b * LH + lh]) * attn_constants[lh * DD + d];
    g_cvec[b * DD + d] = acc;
}

// ---- packed fp32x2 helpers (sm_100+/sm_103a PTX-only) ----
__device__ __forceinline__ unsigned long long bcast2(float x) {
    unsigned long long r;
    unsigned xi = __float_as_uint(x);
    asm("mov.b64 %0, {%1, %1};" : "=l"(r) : "r"(xi));
    return r;
}

__device__ __forceinline__ void ffma2(unsigned long long& c,
                                      unsigned long long a,
                                      unsigned long long b) {
    asm("fma.rn.f32x2 %0, %1, %2, %3;" : "=l"(c) : "l"(a), "l"(b), "l"(c));
}

__device__ __forceinline__ float getf(unsigned long long v, int hf) {
    return __uint_as_float(hf ? (unsigned)(v >> 32) : (unsigned)(v & 0xffffffffu));
}

// Fused: out[b,p,d] = sum_k mask_k*A[b,p,k]*W[k,d] + sum_m mmask*mlp_cache + cvec[b,d]
__global__ __launch_bounds__(NTHREADS)
void fused_kernel(const float* __restrict__ attn_cache,
                  const float* __restrict__ W_O,
                  const float* __restrict__ attn_mask,
                  const float* __restrict__ mlp_cache,
                  const float* __restrict__ mlp_mask,
                  float* __restrict__ out) {
    __shared__ float As[BK][BM];   // [k][p]
    __shared__ float Bs[BK][BN];   // [k][d]
    __shared__ float s_amask[LH];
    __shared__ float s_mmask[MS];

    const int tid = threadIdx.x;
    const int b   = blockIdx.z;
    const int p0  = blockIdx.y * BM;
    const int d0  = blockIdx.x * BN;

    if (tid < LH) s_amask[tid] = attn_mask[b * LH + tid];
    if (tid >= 224 && tid < 224 + MS) s_mmask[tid - 224] = mlp_mask[b * MS + (tid - 224)];
    __syncthreads();

    // compute-thread mapping: 16 p-frags x 16 d-frags; micro-tile 8p x 4d
    const int tp = tid >> 4;       // 0..15
    const int td = tid & 15;       // 0..15
    const int p_base = tp * 8;
    const int d_base = td * 4;

    // A loader mapping: each thread owns one row, 4 consecutive float4s
    const int arow  = tid >> 1;        // 0..127
    const int acol4 = (tid & 1) * 4;   // float4 index 0 or 4 within 32-float chunk
    const float* gA = attn_cache + ((size_t)b * PP + p0 + arow) * KTOT;

    // B loader mapping: 2 float4 per thread
    const int brow0 = tid >> 4;        // 0..15
    const int bcol4 = tid & 15;        // 0..15

    // accumulators: 4 p-pairs x 4 d  (pair = two adjacent p in one f32x2 reg)
    unsigned long long acc[4][4];
#pragma unroll
    for (int i = 0; i < 4; i++)
#pragma unroll
        for (int j = 0; j < 4; j++) acc[i][j] = 0ULL;

    for (int k0 = 0; k0 < KTOT; k0 += BK) {
        // A tile (mask folded in). A 32-aligned K-chunk never crosses a 64-group,
        // so a single mask scalar covers the whole BK chunk.
        const float mk = s_amask[k0 >> 6];
        const float4* gA4 = (const float4*)(gA + k0);
#pragma unroll
        for (int i = 0; i < 4; i++) {
            float4 v = gA4[acol4 + i];
            int c = (acol4 + i) * 4;
            As[c + 0][arow] = v.x * mk;
            As[c + 1][arow] = v.y * mk;
            As[c + 2][arow] = v.z * mk;
            As[c + 3][arow] = v.w * mk;
        }
        // B tile
        {
            const float4* g0 = (const float4*)(W_O + (size_t)(k0 + brow0) * DD + d0);
            *(float4*)&Bs[brow0][bcol4 * 4] = g0[bcol4];
            const float4* g1 = (const float4*)(W_O + (size_t)(k0 + 16 + brow0) * DD + d0);
            *(float4*)&Bs[16 + brow0][bcol4 * 4] = g1[bcol4];
        }
        __syncthreads();

#pragma unroll
        for (int k = 0; k < BK; k++) {
            ulonglong2 a01 = *(const ulonglong2*)&As[k][p_base];      // pairs (p0p1),(p2p3)
            ulonglong2 a23 = *(const ulonglong2*)&As[k][p_base + 4];  // pairs (p4p5),(p6p7)
            float4 bv = *(const float4*)&Bs[k][d_base];
            unsigned long long bp0 = bcast2(bv.x);
            unsigned long long bp1 = bcast2(bv.y);
            unsigned long long bp2 = bcast2(bv.z);
            unsigned long long bp3 = bcast2(bv.w);
            ffma2(acc[0][0], a01.x, bp0); ffma2(acc[0][1], a01.x, bp1);
            ffma2(acc[0][2], a01.x, bp2); ffma2(acc[0][3], a01.x, bp3);
            ffma2(acc[1][0], a01.y, bp0); ffma2(acc[1][1], a01.y, bp1);
            ffma2(acc[1][2], a01.y, bp2); ffma2(acc[1][3], a01.y, bp3);
            ffma2(acc[2][0], a23.x, bp0); ffma2(acc[2][1], a23.x, bp1);
            ffma2(acc[2][2], a23.x, bp2); ffma2(acc[2][3], a23.x, bp3);
            ffma2(acc[3][0], a23.y, bp0); ffma2(acc[3][1], a23.y, bp1);
            ffma2(acc[3][2], a23.y, bp2); ffma2(acc[3][3], a23.y, bp3);
        }
        __syncthreads();
    }

    // Epilogue: + cvec[b,d] + sum_m mlp_mask[b,m]*mlp_cache[b,p,m,d]
    const float4 cv = *(const float4*)(g_cvec + b * DD + d0 + d_base);
    const size_t pstride = (size_t)MS * DD;
    const float* mbase = mlp_cache + ((size_t)b * PP + p0 + p_base) * pstride + d0 + d_base;
    float* obase = out + ((size_t)b * PP + p0 + p_base) * DD + d0 + d_base;

#pragma unroll
    for (int pi = 0; pi < 4; pi++) {
#pragma unroll
        for (int hf = 0; hf < 2; hf++) {
            int pp = pi * 2 + hf;
            float4 r;
            r.x = cv.x + getf(acc[pi][0], hf);
            r.y = cv.y + getf(acc[pi][1], hf);
            r.z = cv.z + getf(acc[pi][2], hf);
            r.w = cv.w + getf(acc[pi][3], hf);
            const float* mrow = mbase + (size_t)pp * pstride;
#pragma unroll
            for (int m = 0; m < MS; m++) {
                float4 mv = *(const float4*)(mrow + (size_t)m * DD);
                float w = s_mmask[m];
                r.x += w * mv.x;
                r.y += w * mv.y;
                r.z += w * mv.z;
                r.w += w * mv.w;
            }
            *(float4*)(obase + (size_t)pp * DD) = r;
        }
    }
}

extern "C" void kernel_launch(void* const* d_in, const int* in_sizes, int n_in,
                              void* d_out, int out_size) {
    const float* mlp_cache      = (const float*)d_in[0];
    const float* attn_cache     = (const float*)d_in[1];
    const float* mlp_mask       = (const float*)d_in[2];
    const float* attn_mask      = (const float*)d_in[3];
    const float* mlp_constants  = (const float*)d_in[4];
    const float* attn_constants = (const float*)d_in[5];
    const float* W_O            = (const float*)d_in[6];
    const float* post_bias      = (const float*)d_in[7];
    float* out = (float*)d_out;

    prep_kernel<<<BB, DD>>>(mlp_mask, attn_mask, mlp_constants, attn_constants, post_bias);

    dim3 grid(DD / BN, PP / BM, BB);   // (12, 4, 16); d-tiles fastest for L2 reuse of A
    fused_kernel<<<grid, NTHREADS>>>(attn_cache, W_O, attn_mask, mlp_cache, mlp_mask, out);
}

// round 9
// speedup vs baseline: 1.9803x; 1.9803x over previous
#include <cuda_runtime.h>
#include <cstdint>

// ---------------- problem constants ----------------
#define BB    16
#define PP    512
#define MS    13
#define DD    768
#define KTOT  9216
#define LH    144

// ---------------- GEMM tiling ----------------
#define BM 128
#define BN 128
#define BK 32
#define STAGES 3
#define KITERS (KTOT/BK)                 // 288
#define TILE_BYTES  (128*128)            // 128 rows x 128B (32 floats)
#define STAGE_BYTES (2*TILE_BYTES)       // A + B
#define DYN_SMEM    (STAGES*STAGE_BYTES) // 98304

// ---------------- device scratch ----------------
__device__ float g_cvec[BB * DD];
__device__ float g_WT[(size_t)DD * KTOT];    // rna(tf32) W_O transposed: [d][k]

// ---------------- helpers ----------------
__device__ __forceinline__ uint32_t smem_u32(const void* p) {
    uint32_t a;
    asm("{ .reg .u64 t; cvta.to.shared.u64 t, %1; cvt.u32.u64 %0, t; }" : "=r"(a) : "l"(p));
    return a;
}
__device__ __forceinline__ float rna_tf32f(float x) {
    uint32_t r;
    asm("cvt.rna.tf32.f32 %0, %1;" : "=r"(r) : "f"(x));
    return __uint_as_float(r);
}
__device__ __forceinline__ uint32_t f2tf32(float x) {
    uint32_t r;
    asm("cvt.rna.tf32.f32 %0, %1;" : "=r"(r) : "f"(x));
    return r;
}
__device__ __forceinline__ void cp16(uint32_t dst, const void* src) {
    asm volatile("cp.async.cg.shared.global [%0], [%1], 16;" :: "r"(dst), "l"(src) : "memory");
}
#define CP_COMMIT()  asm volatile("cp.async.commit_group;" ::: "memory")
#define CP_WAIT1()   asm volatile("cp.async.wait_group 1;" ::: "memory")

__device__ __forceinline__ void mma_tf32(float* d, const uint32_t* a, const uint32_t* b) {
    asm volatile(
        "mma.sync.aligned.m16n8k8.row.col.f32.tf32.tf32.f32 "
        "{%0,%1,%2,%3}, {%4,%5,%6,%7}, {%8,%9}, {%0,%1,%2,%3};"
        : "+f"(d[0]), "+f"(d[1]), "+f"(d[2]), "+f"(d[3])
        : "r"(a[0]), "r"(a[1]), "r"(a[2]), "r"(a[3]), "r"(b[0]), "r"(b[1]));
}

// XOR swizzle: byte offset of float column `kc` in tile row `row` (row = 128B)
__device__ __forceinline__ uint32_t swzf(int row, int kc) {
    return (uint32_t)(row * 128 + ((((kc >> 2) ^ row) & 7) << 4) + ((kc & 3) << 2));
}
// 16B-granule form for producers
__device__ __forceinline__ uint32_t swzg(int row, int g) {
    return (uint32_t)(row * 128 + (((g ^ row) & 7) << 4));
}

// ---------------- prep kernels ----------------
__global__ void prep_cvec(const float* __restrict__ mlp_mask, const float* __restrict__ attn_mask,
                          const float* __restrict__ mlp_constants, const float* __restrict__ attn_constants,
                          const float* __restrict__ post_bias) {
    int b = blockIdx.x, d = threadIdx.x;
    float acc = post_bias[d];
#pragma unroll
    for (int m = 0; m < MS; m++)
        acc += (1.0f - mlp_mask[b * MS + m]) * mlp_constants[m * DD + d];
    for (int lh = 0; lh < LH; lh++)
        acc += (1.0f - attn_mask[b * LH + lh]) * attn_constants[lh * DD + d];
    g_cvec[b * DD + d] = acc;
}

// g_WT[d][k] = rna_tf32(W_O[k][d])
__global__ void prep_wt(const float* __restrict__ W_O) {
    __shared__ float tile[32][33];
    int kt = blockIdx.x * 32, dt = blockIdx.y * 32;
    int tx = threadIdx.x & 31, ty = threadIdx.x >> 5;   // 32x8
#pragma unroll
    for (int i = 0; i < 4; i++)
        tile[ty + 8 * i][tx] = rna_tf32f(W_O[(size_t)(kt + ty + 8 * i) * DD + dt + tx]);
    __syncthreads();
#pragma unroll
    for (int i = 0; i < 4; i++)
        g_WT[(size_t)(dt + ty + 8 * i) * KTOT + kt + tx] = tile[tx][ty + 8 * i];
}

// ---------------- main GEMM (mma.sync tf32, direct-LDS fragments) ----------------
__global__ void __launch_bounds__(128)
gemm_kernel(const float* __restrict__ attn_cache,
            const float* __restrict__ attn_mask,
            const float* __restrict__ mlp_cache,
            const float* __restrict__ mlp_mask,
            float* __restrict__ out) {
    extern __shared__ char smem[];
    const uint32_t dyn = smem_u32(smem);

    __shared__ float s_amask[LH];

    const int tid  = threadIdx.x;
    const int wid  = tid >> 5;
    const int lane = tid & 31;
    const int b  = blockIdx.z;
    const int p0 = blockIdx.y * BM;
    const int d0 = blockIdx.x * BN;

    // FIX (R8 bug): blockDim=128 < LH=144 -> groups 128..143 were never loaded.
    for (int i = tid; i < LH; i += 128) s_amask[i] = attn_mask[b * LH + i];
    __syncthreads();

    // producer: thread t owns A row t and B row t (32 floats per BK chunk each)
    const float* gA = attn_cache + (size_t)(b * PP + p0 + tid) * KTOT;
    const float* gB = g_WT + (size_t)(d0 + tid) * KTOT;

    // warp tiling: 2x2 warps, each 64(m) x 64(n)
    const int wm = (wid >> 1) * 64;
    const int wn = (wid & 1) * 64;

    const int gid = lane >> 2;   // groupID  (0..7)
    const int tig = lane & 3;    // threadID_in_group (0..3)

    float acc[4][8][4];
#pragma unroll
    for (int mf = 0; mf < 4; mf++)
#pragma unroll
        for (int nf = 0; nf < 8; nf++)
#pragma unroll
            for (int j = 0; j < 4; j++) acc[mf][nf][j] = 0.0f;

    // ---- prologue: stage 0,1 ----
#pragma unroll
    for (int s = 0; s < 2; s++) {
        const uint32_t aB = dyn + s * STAGE_BYTES;
        const uint32_t bB = aB + TILE_BYTES;
        const int k0 = s * BK;
#pragma unroll
        for (int g = 0; g < 8; g++) {
            cp16(aB + swzg(tid, g), gA + k0 + g * 4);
            cp16(bB + swzg(tid, g), gB + k0 + g * 4);
        }
        CP_COMMIT();
    }

    // ---- main loop ----
    for (int it = 0; it < KITERS; it++) {
        CP_WAIT1();
        __syncthreads();

        const int s = it % STAGES;
        const char* aS = smem + s * STAGE_BYTES;
        const char* bS = aS + TILE_BYTES;
        const float mk = s_amask[it >> 1];

        if (it + 2 < KITERS) {
            const int s2 = (it + 2) % STAGES;
            const uint32_t aB2 = dyn + s2 * STAGE_BYTES;
            const uint32_t bB2 = aB2 + TILE_BYTES;
            const int k0 = (it + 2) * BK;
#pragma unroll
            for (int g = 0; g < 8; g++) {
                cp16(aB2 + swzg(tid, g), gA + k0 + g * 4);
                cp16(bB2 + swzg(tid, g), gB + k0 + g * 4);
            }
        }
        CP_COMMIT();

#pragma unroll
        for (int ks = 0; ks < 4; ks++) {
            const int kc0 = ks * 8 + tig;       // fragment k columns: kc0 and kc0+4

            // B fragments per PTX ISA table: b0=(k=tig, n=gid), b1=(k=tig+4, n=gid)
            uint32_t bf[8][2];
#pragma unroll
            for (int nf = 0; nf < 8; nf++) {
                const int nrow = wn + nf * 8 + gid;
                bf[nf][0] = *(const uint32_t*)(bS + swzf(nrow, kc0));
                bf[nf][1] = *(const uint32_t*)(bS + swzf(nrow, kc0 + 4));
            }
            // A fragments: a0=(m=gid,k=tig) a1=(m=gid+8,k=tig) a2=(m=gid,k=tig+4) a3=(m=gid+8,k=tig+4)
#pragma unroll
            for (int mf = 0; mf < 4; mf++) {
                const int r0 = wm + mf * 16 + gid;
                uint32_t af[4];
                af[0] = f2tf32(*(const float*)(aS + swzf(r0,     kc0))     * mk);
                af[1] = f2tf32(*(const float*)(aS + swzf(r0 + 8, kc0))     * mk);
                af[2] = f2tf32(*(const float*)(aS + swzf(r0,     kc0 + 4)) * mk);
                af[3] = f2tf32(*(const float*)(aS + swzf(r0 + 8, kc0 + 4)) * mk);
#pragma unroll
                for (int nf = 0; nf < 8; nf++)
                    mma_tf32(acc[mf][nf], af, bf[nf]);
            }
        }
    }

    // ---- epilogue: + cvec + mlp streams, straight from C fragments ----
    float w[MS];
#pragma unroll
    for (int m = 0; m < MS; m++) w[m] = mlp_mask[b * MS + m];

    float2 cv[8];
#pragma unroll
    for (int nf = 0; nf < 8; nf++)
        cv[nf] = *(const float2*)(g_cvec + b * DD + d0 + wn + nf * 8 + 2 * tig);

#pragma unroll
    for (int mf = 0; mf < 4; mf++) {
#pragma unroll
        for (int hi = 0; hi < 2; hi++) {
            const int p = p0 + wm + mf * 16 + hi * 8 + gid;
            const float* mbase = mlp_cache + ((size_t)(b * PP + p) * MS) * DD + d0 + wn + 2 * tig;
            float* obase = out + (size_t)(b * PP + p) * DD + d0 + wn + 2 * tig;
#pragma unroll
            for (int nf = 0; nf < 8; nf++) {
                float2 v;
                v.x = acc[mf][nf][hi * 2 + 0] + cv[nf].x;
                v.y = acc[mf][nf][hi * 2 + 1] + cv[nf].y;
#pragma unroll
                for (int m = 0; m < MS; m++) {
                    const float2 mv = *(const float2*)(mbase + (size_t)m * DD + nf * 8);
                    v.x += w[m] * mv.x;
                    v.y += w[m] * mv.y;
                }
                *(float2*)(obase + nf * 8) = v;
            }
        }
    }
}

// ---------------- launch ----------------
extern "C" void kernel_launch(void* const* d_in, const int* in_sizes, int n_in,
                              void* d_out, int out_size) {
    const float* mlp_cache      = (const float*)d_in[0];
    const float* attn_cache     = (const float*)d_in[1];
    const float* mlp_mask       = (const float*)d_in[2];
    const float* attn_mask      = (const float*)d_in[3];
    const float* mlp_constants  = (const float*)d_in[4];
    const float* attn_constants = (const float*)d_in[5];
    const float* W_O            = (const float*)d_in[6];
    const float* post_bias      = (const float*)d_in[7];
    float* out = (float*)d_out;

    static bool attr_done = false;
    if (!attr_done) {
        cudaFuncSetAttribute(gemm_kernel, cudaFuncAttributeMaxDynamicSharedMemorySize, DYN_SMEM);
        attr_done = true;
    }

    prep_cvec<<<BB, DD>>>(mlp_mask, attn_mask, mlp_constants, attn_constants, post_bias);
    {
        dim3 gw(KTOT / 32, DD / 32);
        prep_wt<<<gw, 256>>>(W_O);
    }
    {
        dim3 grid(DD / BN, PP / BM, BB);   // (6, 4, 16)
        gemm_kernel<<<grid, 128, DYN_SMEM>>>(attn_cache, attn_mask, mlp_cache, mlp_mask, out);
    }
}